// round 1
// baseline (speedup 1.0000x reference)
#include <cuda_runtime.h>

// Problem constants
#define NB   512     // batch
#define NH   256     // hidden
#define NF   64      // feature
#define NT   128     // input_len = target_len
#define G3   768     // 3*NH

// ---------------- scratch (__device__ globals; no allocation allowed) ----------------
__device__ float g_zero[NB * NH];          // never written -> stays zero (initial h)
__device__ float g_hA[NB * NH];
__device__ float g_hB[NB * NH];
__device__ float g_Hdec[NT * NB * NH];     // all decoder hidden states (67MB)
// Prepped weights, layout [jt(16)][k][64] with col c = sec*16 + jl, sec in {r, z, n_i, n_h}
__device__ float g_U1enc[16 * 256 * 64];
__device__ float g_U2enc[16 * 64 * 64];
__device__ float g_U1dec[16 * 256 * 64];
__device__ float g_U1dec0[16 * 256 * 64];
__device__ float g_bias_enc[4 * 256];
__device__ float g_bias_dec[4 * 256];
__device__ float g_bias_dec0[4 * 256];
__device__ float g_gi0[NB * G3];           // decoder step-0 input gates (incl. dec_bih)
__device__ float g_regWT[256 * 64];        // reg_W transposed: [k][f]

// ---------------- prep: build fused weight layouts ----------------
__global__ void k_prep_basic(const float* __restrict__ eWih, const float* __restrict__ eWhh,
                             const float* __restrict__ ebih, const float* __restrict__ ebhh,
                             const float* __restrict__ dWih, const float* __restrict__ dWhh,
                             const float* __restrict__ dbih, const float* __restrict__ dbhh,
                             const float* __restrict__ rW,   const float* __restrict__ rb)
{
    const int stride = gridDim.x * blockDim.x;
    const int tid0 = blockIdx.x * blockDim.x + threadIdx.x;

    const int NU1 = 16 * 256 * 64;
    for (int i = tid0; i < NU1; i += stride) {
        int jt = i / (256 * 64); int rr = i - jt * 256 * 64;
        int k = rr >> 6; int c = rr & 63;
        int sec = c >> 4; int j = jt * 16 + (c & 15);
        float ve = 0.f, vd = 0.f;
        if (sec == 0)      { ve = eWhh[j * 256 + k];         vd = dWhh[j * 256 + k]; }
        else if (sec == 1) { ve = eWhh[(256 + j) * 256 + k]; vd = dWhh[(256 + j) * 256 + k]; }
        else if (sec == 3) { ve = eWhh[(512 + j) * 256 + k]; vd = dWhh[(512 + j) * 256 + k]; }
        g_U1enc[i] = ve; g_U1dec0[i] = vd;
    }
    const int NU2 = 16 * 64 * 64;
    for (int i = tid0; i < NU2; i += stride) {
        int jt = i / (64 * 64); int rr = i - jt * 64 * 64;
        int k = rr >> 6; int c = rr & 63;
        int sec = c >> 4; int j = jt * 16 + (c & 15);
        float v = 0.f;
        if (sec == 0)      v = eWih[j * 64 + k];
        else if (sec == 1) v = eWih[(256 + j) * 64 + k];
        else if (sec == 2) v = eWih[(512 + j) * 64 + k];
        g_U2enc[i] = v;
    }
    for (int i = tid0; i < 256 * 64; i += stride) {
        int k = i >> 6, f = i & 63;
        g_regWT[i] = rW[f * 256 + k];
    }
    for (int i = tid0; i < 1024; i += stride) {
        int sec = i >> 8, j = i & 255;
        float be, bd0, bd;
        if (sec <= 1) {
            int n = sec * 256 + j;
            be = ebih[n] + ebhh[n];
            bd0 = dbhh[n];
            float bc = dbih[n];
            for (int f = 0; f < 64; f++) bc += rb[f] * dWih[n * 64 + f];
            bd = bc + dbhh[n];
        } else if (sec == 2) {           // n-gate, input part
            int n = 512 + j;
            be = ebih[n];
            bd0 = 0.f;                   // step-0 gi comes via g_gi0 (includes dbih)
            float bc = dbih[n];
            for (int f = 0; f < 64; f++) bc += rb[f] * dWih[n * 64 + f];
            bd = bc;
        } else {                          // n-gate, hidden part
            int n = 512 + j;
            be = ebhh[n]; bd0 = dbhh[n]; bd = dbhh[n];
        }
        g_bias_enc[i] = be; g_bias_dec0[i] = bd0; g_bias_dec[i] = bd;
    }
}

// Decoder combined weights: Wcomb = reg_W^T @ dec_Wih^T folded with dec_Whh^T
__global__ void k_prep_dec(const float* __restrict__ dWih, const float* __restrict__ dWhh,
                           const float* __restrict__ rW)
{
    int i = blockIdx.x * blockDim.x + threadIdx.x;
    if (i >= 16 * 256 * 64) return;
    int jt = i / (256 * 64); int rr = i - jt * 256 * 64;
    int k = rr >> 6; int c = rr & 63;
    int sec = c >> 4; int j = jt * 16 + (c & 15);
    float v;
    if (sec == 3) {
        v = dWhh[(512 + j) * 256 + k];
    } else {
        int n = sec * 256 + j;
        float wc = 0.f;
        #pragma unroll
        for (int f = 0; f < 64; f++) wc += rW[f * 256 + k] * dWih[n * 64 + f];
        v = wc + ((sec < 2) ? dWhh[n * 256 + k] : 0.f);
    }
    g_U1dec[i] = v;
}

// Decoder step-0 input gates from x[:,127,:]
__global__ void k_gi0(const float* __restrict__ x, const float* __restrict__ dWih,
                      const float* __restrict__ dbih)
{
    int i = blockIdx.x * blockDim.x + threadIdx.x;
    if (i >= NB * G3) return;
    int b = i / G3, n = i - b * G3;
    const float* xr = x + (b * 256 + 127) * 64;
    float s = dbih[n];
    #pragma unroll
    for (int f = 0; f < 64; f++) s += xr[f] * dWih[n * 64 + f];
    g_gi0[i] = s;
}

// ---------------- fused GRU step ----------------
// Block tile: 64 rows (batch) x 16 hidden units x 4 gate sections. 128 threads.
// Thread tile: 4 (M) x 8 (N = 2 j x 4 sections).
#define FMA_BLOCK()                                                              \
    {                                                                            \
        float h0 = hs[mthr * 4 + 0][kk];                                         \
        float h1 = hs[mthr * 4 + 1][kk];                                         \
        float h2 = hs[mthr * 4 + 2][kk];                                         \
        float h3 = hs[mthr * 4 + 3][kk];                                         \
        float2 u0 = *(const float2*)&Us[kk][ 0 + 2 * nthr];                      \
        float2 u1 = *(const float2*)&Us[kk][16 + 2 * nthr];                      \
        float2 u2 = *(const float2*)&Us[kk][32 + 2 * nthr];                      \
        float2 u3 = *(const float2*)&Us[kk][48 + 2 * nthr];                      \
        acc[0][0] += h0 * u0.x; acc[0][1] += h0 * u0.y;                          \
        acc[0][2] += h0 * u1.x; acc[0][3] += h0 * u1.y;                          \
        acc[0][4] += h0 * u2.x; acc[0][5] += h0 * u2.y;                          \
        acc[0][6] += h0 * u3.x; acc[0][7] += h0 * u3.y;                          \
        acc[1][0] += h1 * u0.x; acc[1][1] += h1 * u0.y;                          \
        acc[1][2] += h1 * u1.x; acc[1][3] += h1 * u1.y;                          \
        acc[1][4] += h1 * u2.x; acc[1][5] += h1 * u2.y;                          \
        acc[1][6] += h1 * u3.x; acc[1][7] += h1 * u3.y;                          \
        acc[2][0] += h2 * u0.x; acc[2][1] += h2 * u0.y;                          \
        acc[2][2] += h2 * u1.x; acc[2][3] += h2 * u1.y;                          \
        acc[2][4] += h2 * u2.x; acc[2][5] += h2 * u2.y;                          \
        acc[2][6] += h2 * u3.x; acc[2][7] += h2 * u3.y;                          \
        acc[3][0] += h3 * u0.x; acc[3][1] += h3 * u0.y;                          \
        acc[3][2] += h3 * u1.x; acc[3][3] += h3 * u1.y;                          \
        acc[3][4] += h3 * u2.x; acc[3][5] += h3 * u2.y;                          \
        acc[3][6] += h3 * u3.x; acc[3][7] += h3 * u3.y;                          \
    }

__global__ __launch_bounds__(128) void k_step(
    const float* __restrict__ hin,
    const float* __restrict__ U1,    // [16][256][64]
    const float* __restrict__ xt,    // encoder: x slice (row stride xstride); else null
    int xstride,
    const float* __restrict__ U2,    // [16][64][64] or null
    const float* __restrict__ gi0,   // [NB][768] or null (decoder step 0)
    const float* __restrict__ bias,  // [4][256]
    float* __restrict__ hout)
{
    __shared__ float hs[64][65];
    __shared__ float Us[64][64];
    const int tid = threadIdx.x;
    const int nthr = tid & 7;
    const int mthr = tid >> 3;
    const int m0 = blockIdx.x * 64;
    const int jt = blockIdx.y;

    float acc[4][8];
    #pragma unroll
    for (int a = 0; a < 4; a++)
        #pragma unroll
        for (int b2 = 0; b2 < 8; b2++) acc[a][b2] = 0.f;

    const float* U1b = U1 + jt * (256 * 64);

    for (int kc = 0; kc < 256; kc += 64) {
        #pragma unroll
        for (int i = 0; i < 8; i++) {
            int g = i * 128 + tid; int m = g >> 4, kq = g & 15;
            float4 v = *(const float4*)(hin + (m0 + m) * 256 + kc + kq * 4);
            hs[m][kq * 4 + 0] = v.x; hs[m][kq * 4 + 1] = v.y;
            hs[m][kq * 4 + 2] = v.z; hs[m][kq * 4 + 3] = v.w;
        }
        #pragma unroll
        for (int i = 0; i < 8; i++) {
            int g = i * 128 + tid; int k = g >> 4, c = g & 15;
            *(float4*)&Us[k][c * 4] = *(const float4*)(U1b + (kc + k) * 64 + c * 4);
        }
        __syncthreads();
        #pragma unroll 4
        for (int kk = 0; kk < 64; kk++) FMA_BLOCK();
        __syncthreads();
    }

    if (U2) {  // encoder: fold x_t @ Wih^T (K = 64)
        #pragma unroll
        for (int i = 0; i < 8; i++) {
            int g = i * 128 + tid; int m = g >> 4, kq = g & 15;
            float4 v = *(const float4*)(xt + (m0 + m) * (long)xstride + kq * 4);
            hs[m][kq * 4 + 0] = v.x; hs[m][kq * 4 + 1] = v.y;
            hs[m][kq * 4 + 2] = v.z; hs[m][kq * 4 + 3] = v.w;
        }
        #pragma unroll
        for (int i = 0; i < 8; i++) {
            int g = i * 128 + tid; int k = g >> 4, c = g & 15;
            *(float4*)&Us[k][c * 4] = *(const float4*)(U2 + jt * (64 * 64) + k * 64 + c * 4);
        }
        __syncthreads();
        #pragma unroll 4
        for (int kk = 0; kk < 64; kk++) FMA_BLOCK();
        __syncthreads();
    }

    // Fused GRU gate epilogue
    #pragma unroll
    for (int m = 0; m < 4; m++) {
        int row = m0 + mthr * 4 + m;
        #pragma unroll
        for (int jp = 0; jp < 2; jp++) {
            int j = jt * 16 + 2 * nthr + jp;
            float A  = acc[m][0 + jp];   // r (combined)
            float Bv = acc[m][2 + jp];   // z (combined)
            float C  = acc[m][4 + jp];   // n input part
            float D  = acc[m][6 + jp];   // n hidden part
            if (gi0) {
                const float* gp = gi0 + row * G3;
                A += gp[j]; Bv += gp[256 + j]; C += gp[512 + j];
            }
            A += bias[j]; Bv += bias[256 + j]; C += bias[512 + j]; D += bias[768 + j];
            float r = 1.f / (1.f + expf(-A));
            float z = 1.f / (1.f + expf(-Bv));
            float n = tanhf(fmaf(r, D, C));
            float hold = hin[row * 256 + j];
            hout[row * 256 + j] = (1.f - z) * n + z * hold;
        }
    }
}

// ---------------- final output projection: out[b][t][f] = Hdec[t][b][:] @ reg_W^T + reg_b
__global__ __launch_bounds__(256) void k_out(const float* __restrict__ Hdec,
                                             const float* __restrict__ regWT,
                                             const float* __restrict__ rb,
                                             float* __restrict__ out)
{
    __shared__ float hs[32][260];
    const int tid = threadIdx.x;
    const int r0 = blockIdx.x * 32;
    #pragma unroll
    for (int i = 0; i < 8; i++) {
        int g = i * 256 + tid; int row = g >> 6, kq = g & 63;
        *(float4*)&hs[row][kq * 4] = *(const float4*)(Hdec + (size_t)(r0 + row) * 256 + kq * 4);
    }
    __syncthreads();
    const int row = tid >> 3;
    const int f0 = (tid & 7) * 8;
    float acc[8];
    #pragma unroll
    for (int q = 0; q < 8; q++) acc[q] = rb[f0 + q];
    for (int k = 0; k < 256; k++) {
        float hv = hs[row][k];
        float4 w0 = *(const float4*)(regWT + k * 64 + f0);
        float4 w1 = *(const float4*)(regWT + k * 64 + f0 + 4);
        acc[0] += hv * w0.x; acc[1] += hv * w0.y; acc[2] += hv * w0.z; acc[3] += hv * w0.w;
        acc[4] += hv * w1.x; acc[5] += hv * w1.y; acc[6] += hv * w1.z; acc[7] += hv * w1.w;
    }
    int rr = r0 + row;
    int b = rr & 511;
    int t = rr >> 9;
    float* o = out + ((size_t)b * 128 + t) * 64 + f0;
    #pragma unroll
    for (int q = 0; q < 8; q++) o[q] = acc[q];
}

// ---------------- launch ----------------
extern "C" void kernel_launch(void* const* d_in, const int* in_sizes, int n_in,
                              void* d_out, int out_size)
{
    (void)in_sizes; (void)n_in; (void)out_size;
    const float* x    = (const float*)d_in[0];
    const float* eWih = (const float*)d_in[1];
    const float* eWhh = (const float*)d_in[2];
    const float* ebih = (const float*)d_in[3];
    const float* ebhh = (const float*)d_in[4];
    const float* dWih = (const float*)d_in[5];
    const float* dWhh = (const float*)d_in[6];
    const float* dbih = (const float*)d_in[7];
    const float* dbhh = (const float*)d_in[8];
    const float* rW   = (const float*)d_in[9];
    const float* rb   = (const float*)d_in[10];
    float* out = (float*)d_out;

    float *pZero, *pA, *pB, *pHdec, *pU1e, *pU2e, *pU1d, *pU1d0;
    float *pBe, *pBd, *pBd0, *pGi0, *pWT;
    cudaGetSymbolAddress((void**)&pZero, g_zero);
    cudaGetSymbolAddress((void**)&pA,    g_hA);
    cudaGetSymbolAddress((void**)&pB,    g_hB);
    cudaGetSymbolAddress((void**)&pHdec, g_Hdec);
    cudaGetSymbolAddress((void**)&pU1e,  g_U1enc);
    cudaGetSymbolAddress((void**)&pU2e,  g_U2enc);
    cudaGetSymbolAddress((void**)&pU1d,  g_U1dec);
    cudaGetSymbolAddress((void**)&pU1d0, g_U1dec0);
    cudaGetSymbolAddress((void**)&pBe,   g_bias_enc);
    cudaGetSymbolAddress((void**)&pBd,   g_bias_dec);
    cudaGetSymbolAddress((void**)&pBd0,  g_bias_dec0);
    cudaGetSymbolAddress((void**)&pGi0,  g_gi0);
    cudaGetSymbolAddress((void**)&pWT,   g_regWT);

    k_prep_basic<<<256, 256>>>(eWih, eWhh, ebih, ebhh, dWih, dWhh, dbih, dbhh, rW, rb);
    k_prep_dec<<<(16 * 256 * 64 + 255) / 256, 256>>>(dWih, dWhh, rW);
    k_gi0<<<(NB * G3 + 255) / 256, 256>>>(x, dWih, dbih);

    dim3 grid(8, 16), blk(128);
    const float* h = pZero;
    for (int t = 0; t < NT; t++) {             // encoder
        float* ho = (t & 1) ? pB : pA;
        k_step<<<grid, blk>>>(h, pU1e, x + t * 64, 256 * 64, pU2e, nullptr, pBe, ho);
        h = ho;
    }
    for (int t = 0; t < NT; t++) {             // decoder (input recurrence folded into U1dec)
        float* ho = pHdec + (size_t)t * NB * NH;
        if (t == 0)
            k_step<<<grid, blk>>>(h, pU1d0, nullptr, 0, nullptr, pGi0, pBd0, ho);
        else
            k_step<<<grid, blk>>>(h, pU1d, nullptr, 0, nullptr, nullptr, pBd, ho);
        h = ho;
    }
    k_out<<<(NB * NT) / 32, 256>>>(pHdec, pWT, rb, out);
}

// round 3
// speedup vs baseline: 2.2702x; 2.2702x over previous
#include <cuda_runtime.h>
#include <cuda_bf16.h>
#include <cstdint>

#define NB 512
#define NH 256
#define NT 128
#define G3 768

// ---------------- device scratch ----------------
__device__ __align__(128) float g_h0[NB*NH];
__device__ __align__(128) float g_h1[NB*NH];
__device__ __align__(128) float g_hZ[NB*NH];            // stays zero
__device__ __align__(128) float g_Hdec[NT*NB*NH];
__device__ __align__(128) __nv_bfloat16 g_Ah0[NB*NH], g_Al0[NB*NH];
__device__ __align__(128) __nv_bfloat16 g_Ah1[NB*NH], g_Al1[NB*NH];
__device__ __align__(128) __nv_bfloat16 g_AhZ[NB*NH], g_AlZ[NB*NH];   // stay zero
__device__ __align__(128) __nv_bfloat16 g_Xh[256*NB*64], g_Xl[256*NB*64];
// B weights in mma fragment order: per jt: [part(2)][chunk][ng(8)][lane(32)][reg(2)] u32
__device__ __align__(128) uint32_t g_eB[16*20480];      // NCH=20
__device__ __align__(128) uint32_t g_dB[16*16384];      // NCH=16
__device__ __align__(128) uint32_t g_d0B[16*16384];
__device__ float g_bias_enc[1024], g_bias_dec[1024], g_bias_dec0[1024];
__device__ float g_gi0[NB*G3];
__device__ float g_regWT[256*64];

// ---------------- prep helpers ----------------
__device__ __forceinline__ uint32_t pack_split(float v0, float v1, int part) {
    __nv_bfloat16 h0 = __float2bfloat16(v0), h1 = __float2bfloat16(v1);
    if (part == 0)
        return (uint32_t)__bfloat16_as_ushort(h0) | ((uint32_t)__bfloat16_as_ushort(h1) << 16);
    __nv_bfloat16 l0 = __float2bfloat16(v0 - __bfloat162float(h0));
    __nv_bfloat16 l1 = __float2bfloat16(v1 - __bfloat162float(h1));
    return (uint32_t)__bfloat16_as_ushort(l0) | ((uint32_t)__bfloat16_as_ushort(l1) << 16);
}

__device__ __forceinline__ float enc_w(const float* eWih, const float* eWhh,
                                       int sec, int j, int k) {
    if (k < 256) {
        if (sec == 0) return eWhh[j*256 + k];
        if (sec == 1) return eWhh[(256 + j)*256 + k];
        if (sec == 3) return eWhh[(512 + j)*256 + k];
        return 0.f;
    } else {
        int f = k - 256;
        if (sec == 0) return eWih[j*64 + f];
        if (sec == 1) return eWih[(256 + j)*64 + f];
        if (sec == 2) return eWih[(512 + j)*64 + f];
        return 0.f;
    }
}

__global__ void k_prep_frag(const float* __restrict__ eWih, const float* __restrict__ eWhh,
                            const float* __restrict__ dWih, const float* __restrict__ dWhh,
                            const float* __restrict__ rW)
{
    const int stride = gridDim.x * blockDim.x;
    const int t0 = blockIdx.x * blockDim.x + threadIdx.x;

    // encoder: NCH=20, per-jt u32 = 2*20*8*32*2 = 20480
    for (int i = t0; i < 16*20480; i += stride) {
        int jt = i / 20480, rem = i % 20480;
        int part = rem / 10240; rem %= 10240;
        int ch = rem / 512;     rem %= 512;
        int ng = rem / 64;      rem %= 64;
        int lane = rem >> 1, r = rem & 1;
        int k  = ch*16 + (lane & 3)*2 + r*8;
        int nl = ng*8 + (lane >> 2);
        int sec = nl & 3, j = jt*16 + (nl >> 2);
        float v0 = enc_w(eWih, eWhh, sec, j, k);
        float v1 = enc_w(eWih, eWhh, sec, j, k + 1);
        g_eB[i] = pack_split(v0, v1, part);
    }

    // decoder folded + dec step0: NCH=16, per-jt u32 = 16384
    for (int i = t0; i < 16*16384; i += stride) {
        int jt = i / 16384, rem = i % 16384;
        int part = rem / 8192; rem %= 8192;
        int ch = rem / 512;    rem %= 512;
        int ng = rem / 64;     rem %= 64;
        int lane = rem >> 1, r = rem & 1;
        int k  = ch*16 + (lane & 3)*2 + r*8;
        int nl = ng*8 + (lane >> 2);
        int sec = nl & 3, j = jt*16 + (nl >> 2);
        float v0, v1, w0, w1;
        if (sec == 3) {
            v0 = w0 = dWhh[(512 + j)*256 + k];
            v1 = w1 = dWhh[(512 + j)*256 + k + 1];
        } else {
            int n = sec*256 + j;
            float c0 = 0.f, c1 = 0.f;
            #pragma unroll
            for (int f = 0; f < 64; f++) {
                float wi = dWih[n*64 + f];
                c0 += rW[f*256 + k]     * wi;
                c1 += rW[f*256 + k + 1] * wi;
            }
            float hh0 = (sec < 2) ? dWhh[n*256 + k]     : 0.f;
            float hh1 = (sec < 2) ? dWhh[n*256 + k + 1] : 0.f;
            v0 = c0 + hh0; v1 = c1 + hh1;
            w0 = hh0;      w1 = hh1;
        }
        g_dB[i]  = pack_split(v0, v1, part);
        g_d0B[i] = pack_split(w0, w1, part);
    }
}

// x -> bf16 hi/lo, [t][m][f]
__global__ void k_prep_x(const float* __restrict__ x)
{
    const int stride = gridDim.x * blockDim.x;
    for (int i = blockIdx.x * blockDim.x + threadIdx.x; i < 256*512*64; i += stride) {
        int t = i / (512*64); int rem = i - t*512*64;
        int m = rem >> 6, f = rem & 63;
        float v = x[(m*256 + t)*64 + f];
        __nv_bfloat16 hb = __float2bfloat16(v);
        g_Xh[i] = hb;
        g_Xl[i] = __float2bfloat16(v - __bfloat162float(hb));
    }
}

__global__ void k_prep_bias(const float* __restrict__ ebih, const float* __restrict__ ebhh,
                            const float* __restrict__ dWih,
                            const float* __restrict__ dbih, const float* __restrict__ dbhh,
                            const float* __restrict__ rW,   const float* __restrict__ rb)
{
    const int stride = gridDim.x * blockDim.x;
    const int t0 = blockIdx.x * blockDim.x + threadIdx.x;
    for (int i = t0; i < 256*64; i += stride) {
        int k = i >> 6, f = i & 63;
        g_regWT[i] = rW[f*256 + k];
    }
    for (int i = t0; i < 1024; i += stride) {
        int sec = i >> 8, j = i & 255;
        float be, bd0, bd;
        if (sec <= 1) {
            int n = sec*256 + j;
            be = ebih[n] + ebhh[n];
            bd0 = dbhh[n];
            float bc = dbih[n];
            for (int f = 0; f < 64; f++) bc += rb[f]*dWih[n*64 + f];
            bd = bc + dbhh[n];
        } else if (sec == 2) {
            int n = 512 + j;
            be = ebih[n]; bd0 = 0.f;
            float bc = dbih[n];
            for (int f = 0; f < 64; f++) bc += rb[f]*dWih[n*64 + f];
            bd = bc;
        } else {
            int n = 512 + j;
            be = ebhh[n]; bd0 = dbhh[n]; bd = dbhh[n];
        }
        g_bias_enc[i] = be; g_bias_dec0[i] = bd0; g_bias_dec[i] = bd;
    }
}

__global__ void k_gi0(const float* __restrict__ x, const float* __restrict__ dWih,
                      const float* __restrict__ dbih)
{
    int i = blockIdx.x * blockDim.x + threadIdx.x;
    if (i >= NB*G3) return;
    int b = i / G3, n = i - b*G3;
    const float* xr = x + (b*256 + 127)*64;
    float s = dbih[n];
    #pragma unroll
    for (int f = 0; f < 64; f++) s += xr[f]*dWih[n*64 + f];
    g_gi0[i] = s;
}

// ---------------- fused GRU step via mma.sync ----------------
#define ASTRIDE 328                     // A smem row stride in bf16 elems (pad 8)
#define APS (64*ASTRIDE*2)              // bytes per A precision part = 41984
#define SB_OFF   (2*APS)                // 83968
#define SHOLD_OFF (SB_OFF + 81920)      // 165888
#define SH_OFF   (SHOLD_OFF + 4096)     // 169984
#define SMEM_BYTES (SH_OFF + 4096)      // 174080

#define MMA16816(d, a, b0, b1) \
    asm volatile("mma.sync.aligned.m16n8k16.row.col.f32.bf16.bf16.f32 " \
        "{%0,%1,%2,%3},{%4,%5,%6,%7},{%8,%9},{%0,%1,%2,%3};" \
        : "+f"((d)[0]), "+f"((d)[1]), "+f"((d)[2]), "+f"((d)[3]) \
        : "r"((a)[0]), "r"((a)[1]), "r"((a)[2]), "r"((a)[3]), "r"(b0), "r"(b1))

template<int NCH, bool HASX>
__global__ __launch_bounds__(256, 1) void k_step(
    const __nv_bfloat16* __restrict__ Ah, const __nv_bfloat16* __restrict__ Al,
    const __nv_bfloat16* __restrict__ Xh, const __nv_bfloat16* __restrict__ Xl,
    const uint4* __restrict__ Bfrag,
    const float* __restrict__ gi0, const float* __restrict__ bias,
    const float* __restrict__ h_old, float* __restrict__ h_out,
    __nv_bfloat16* __restrict__ Aoh, __nv_bfloat16* __restrict__ Aol)
{
    extern __shared__ char sm[];
    const int tid = threadIdx.x;
    const int m0 = blockIdx.x * 64;
    const int jt = blockIdx.y;

    uint4* sA4h  = (uint4*)sm;
    uint4* sA4l  = (uint4*)(sm + APS);
    uint4* sB4   = (uint4*)(sm + SB_OFF);
    float* sHold = (float*)(sm + SHOLD_OFF);
    float* sH    = (float*)(sm + SH_OFF);

    // ---- stage B fragments (already fragment-ordered in gmem) ----
    const uint4* Bsrc = Bfrag + (size_t)jt * (NCH*256);
    #pragma unroll
    for (int i = tid; i < NCH*256; i += 256) sB4[i] = Bsrc[i];

    // ---- stage A hi/lo (row-major, padded rows) ----
    const uint4* Ah4 = (const uint4*)Ah;
    const uint4* Al4 = (const uint4*)Al;
    #pragma unroll
    for (int i = tid; i < 2048; i += 256) {
        int r = i >> 5, c = i & 31;
        sA4h[r*41 + c] = Ah4[(m0 + r)*32 + c];
        sA4l[r*41 + c] = Al4[(m0 + r)*32 + c];
    }
    if (HASX) {
        const uint4* Xh4 = (const uint4*)Xh;
        const uint4* Xl4 = (const uint4*)Xl;
        #pragma unroll
        for (int i = tid; i < 512; i += 256) {
            int r = i >> 3, c = i & 7;
            sA4h[r*41 + 32 + c] = Xh4[(m0 + r)*8 + c];
            sA4l[r*41 + 32 + c] = Xl4[(m0 + r)*8 + c];
        }
    }
    // ---- stage h_old tile ----
    {
        int r = tid >> 2, c = tid & 3;
        ((uint4*)sHold)[tid] = *(const uint4*)&h_old[(m0 + r)*256 + jt*16 + c*4];
    }
    __syncthreads();

    const int lane = tid & 31;
    const int wid  = tid >> 5;
    const int wm = wid & 1, wn = wid >> 1;      // 2 x 4 warp grid
    const int qr = lane >> 2, qp = lane & 3;

    float acc[2][2][4];
    #pragma unroll
    for (int a = 0; a < 2; a++)
        #pragma unroll
        for (int b = 0; b < 2; b++)
            #pragma unroll
            for (int c = 0; c < 4; c++) acc[a][b][c] = 0.f;

    const uint32_t* sBu = (const uint32_t*)(sm + SB_OFF);

    #pragma unroll 4
    for (int ch = 0; ch < NCH; ch++) {
        const int c2 = ch*16 + qp*2;
        uint32_t ah[2][4], al[2][4];
        #pragma unroll
        for (int mi = 0; mi < 2; mi++) {
            const int rr = wm*32 + mi*16 + qr;
            const char* p = sm + (rr*ASTRIDE + c2)*2;
            ah[mi][0] = *(const uint32_t*)(p);
            ah[mi][1] = *(const uint32_t*)(p + 8*ASTRIDE*2);
            ah[mi][2] = *(const uint32_t*)(p + 16);
            ah[mi][3] = *(const uint32_t*)(p + 8*ASTRIDE*2 + 16);
            al[mi][0] = *(const uint32_t*)(p + APS);
            al[mi][1] = *(const uint32_t*)(p + APS + 8*ASTRIDE*2);
            al[mi][2] = *(const uint32_t*)(p + APS + 16);
            al[mi][3] = *(const uint32_t*)(p + APS + 8*ASTRIDE*2 + 16);
        }
        #pragma unroll
        for (int ni = 0; ni < 2; ni++) {
            const int ng = wn*2 + ni;
            const uint32_t* bp = sBu + ((ch*8 + ng)*32 + lane)*2;
            uint32_t bh0 = bp[0], bh1 = bp[1];
            uint32_t bl0 = bp[NCH*512], bl1 = bp[NCH*512 + 1];
            #pragma unroll
            for (int mi = 0; mi < 2; mi++) {
                MMA16816(acc[mi][ni], ah[mi], bh0, bh1);
                MMA16816(acc[mi][ni], ah[mi], bl0, bl1);
                MMA16816(acc[mi][ni], al[mi], bh0, bh1);
            }
        }
    }

    // ---- epilogue: combine gate pairs across adjacent lanes, fuse GRU ----
    #pragma unroll
    for (int mi = 0; mi < 2; mi++) {
        #pragma unroll
        for (int ni = 0; ni < 2; ni++) {
            float d0 = acc[mi][ni][0], d1 = acc[mi][ni][1];
            float d2 = acc[mi][ni][2], d3 = acc[mi][ni][3];
            float e0 = __shfl_xor_sync(0xffffffffu, d0, 1);
            float e1 = __shfl_xor_sync(0xffffffffu, d1, 1);
            float e2 = __shfl_xor_sync(0xffffffffu, d2, 1);
            float e3 = __shfl_xor_sync(0xffffffffu, d3, 1);
            if ((qp & 1) == 0) {
                const int jloc = wn*4 + ni*2 + (qp >> 1);
                const int j = jt*16 + jloc;
                const float b0 = bias[j], b1 = bias[256 + j];
                const float b2 = bias[512 + j], b3 = bias[768 + j];
                #pragma unroll
                for (int hf = 0; hf < 2; hf++) {
                    const int mloc = wm*32 + mi*16 + qr + hf*8;
                    float ga = (hf ? d2 : d0) + b0;   // r preact
                    float gb = (hf ? d3 : d1) + b1;   // z preact
                    float gc = (hf ? e2 : e0) + b2;   // n input part
                    float gd = (hf ? e3 : e1) + b3;   // n hidden part
                    if (gi0) {
                        const float* gp = gi0 + (size_t)(m0 + mloc)*G3;
                        ga += gp[j]; gb += gp[256 + j]; gc += gp[512 + j];
                    }
                    float rg = 1.f/(1.f + __expf(-ga));
                    float zg = 1.f/(1.f + __expf(-gb));
                    float nn = tanhf(fmaf(rg, gd, gc));
                    float hv = (1.f - zg)*nn + zg*sHold[mloc*16 + jloc];
                    sH[mloc*16 + jloc] = hv;
                }
            }
        }
    }
    __syncthreads();

    // ---- coalesced outputs ----
    {
        int r = tid >> 2, c = tid & 3;
        *(float4*)&h_out[(m0 + r)*256 + jt*16 + c*4] = *(float4*)&sH[r*16 + c*4];
    }
    if (tid < 64) {
        int r = tid;
        union { uint4 v; ushort s[8]; } ph[2], pl[2];
        #pragma unroll
        for (int c = 0; c < 16; c++) {
            float f = sH[r*16 + c];
            __nv_bfloat16 hb = __float2bfloat16(f);
            __nv_bfloat16 lb = __float2bfloat16(f - __bfloat162float(hb));
            ph[c >> 3].s[c & 7] = __bfloat16_as_ushort(hb);
            pl[c >> 3].s[c & 7] = __bfloat16_as_ushort(lb);
        }
        uint4* dh = (uint4*)(Aoh + (size_t)(m0 + r)*256 + jt*16);
        uint4* dl = (uint4*)(Aol + (size_t)(m0 + r)*256 + jt*16);
        dh[0] = ph[0].v; dh[1] = ph[1].v;
        dl[0] = pl[0].v; dl[1] = pl[1].v;
    }
}

// ---------------- final projection ----------------
__global__ __launch_bounds__(256) void k_out(const float* __restrict__ Hdec,
                                             const float* __restrict__ regWT,
                                             const float* __restrict__ rb,
                                             float* __restrict__ out)
{
    __shared__ float hs[32][260];
    const int tid = threadIdx.x;
    const int r0 = blockIdx.x * 32;
    #pragma unroll
    for (int i = 0; i < 8; i++) {
        int g = i*256 + tid; int row = g >> 6, kq = g & 63;
        *(float4*)&hs[row][kq*4] = *(const float4*)(Hdec + (size_t)(r0 + row)*256 + kq*4);
    }
    __syncthreads();
    const int row = tid >> 3;
    const int f0 = (tid & 7)*8;
    float acc[8];
    #pragma unroll
    for (int q = 0; q < 8; q++) acc[q] = rb[f0 + q];
    for (int k = 0; k < 256; k++) {
        float hvv = hs[row][k];
        float4 w0 = *(const float4*)(regWT + k*64 + f0);
        float4 w1 = *(const float4*)(regWT + k*64 + f0 + 4);
        acc[0] += hvv*w0.x; acc[1] += hvv*w0.y; acc[2] += hvv*w0.z; acc[3] += hvv*w0.w;
        acc[4] += hvv*w1.x; acc[5] += hvv*w1.y; acc[6] += hvv*w1.z; acc[7] += hvv*w1.w;
    }
    int rr = r0 + row;
    int b = rr & 511;
    int t = rr >> 9;
    float* o = out + ((size_t)b*128 + t)*64 + f0;
    #pragma unroll
    for (int q = 0; q < 8; q++) o[q] = acc[q];
}

// ---------------- launch ----------------
extern "C" void kernel_launch(void* const* d_in, const int* in_sizes, int n_in,
                              void* d_out, int out_size)
{
    (void)in_sizes; (void)n_in; (void)out_size;
    const float* x    = (const float*)d_in[0];
    const float* eWih = (const float*)d_in[1];
    const float* eWhh = (const float*)d_in[2];
    const float* ebih = (const float*)d_in[3];
    const float* ebhh = (const float*)d_in[4];
    const float* dWih = (const float*)d_in[5];
    const float* dWhh = (const float*)d_in[6];
    const float* dbih = (const float*)d_in[7];
    const float* dbhh = (const float*)d_in[8];
    const float* rW   = (const float*)d_in[9];
    const float* rb   = (const float*)d_in[10];
    float* out = (float*)d_out;

    float *ph0, *ph1, *phZ, *pHdec, *pBe, *pBd, *pBd0, *pGi0, *pWT;
    __nv_bfloat16 *pAh0, *pAl0, *pAh1, *pAl1, *pAhZ, *pAlZ, *pXh, *pXl;
    uint32_t *peB, *pdB, *pd0B;
    cudaGetSymbolAddress((void**)&ph0, g_h0);
    cudaGetSymbolAddress((void**)&ph1, g_h1);
    cudaGetSymbolAddress((void**)&phZ, g_hZ);
    cudaGetSymbolAddress((void**)&pHdec, g_Hdec);
    cudaGetSymbolAddress((void**)&pAh0, g_Ah0);
    cudaGetSymbolAddress((void**)&pAl0, g_Al0);
    cudaGetSymbolAddress((void**)&pAh1, g_Ah1);
    cudaGetSymbolAddress((void**)&pAl1, g_Al1);
    cudaGetSymbolAddress((void**)&pAhZ, g_AhZ);
    cudaGetSymbolAddress((void**)&pAlZ, g_AlZ);
    cudaGetSymbolAddress((void**)&pXh, g_Xh);
    cudaGetSymbolAddress((void**)&pXl, g_Xl);
    cudaGetSymbolAddress((void**)&peB, g_eB);
    cudaGetSymbolAddress((void**)&pdB, g_dB);
    cudaGetSymbolAddress((void**)&pd0B, g_d0B);
    cudaGetSymbolAddress((void**)&pBe, g_bias_enc);
    cudaGetSymbolAddress((void**)&pBd, g_bias_dec);
    cudaGetSymbolAddress((void**)&pBd0, g_bias_dec0);
    cudaGetSymbolAddress((void**)&pGi0, g_gi0);
    cudaGetSymbolAddress((void**)&pWT, g_regWT);

    cudaFuncSetAttribute(k_step<20, true>,  cudaFuncAttributeMaxDynamicSharedMemorySize, SMEM_BYTES);
    cudaFuncSetAttribute(k_step<16, false>, cudaFuncAttributeMaxDynamicSharedMemorySize, SMEM_BYTES);

    k_prep_frag<<<1024, 256>>>(eWih, eWhh, dWih, dWhh, rW);
    k_prep_x<<<2048, 256>>>(x);
    k_prep_bias<<<128, 256>>>(ebih, ebhh, dWih, dbih, dbhh, rW, rb);
    k_gi0<<<(NB*G3 + 255)/256, 256>>>(x, dWih, dbih);

    __nv_bfloat16* AH[2] = { pAh0, pAh1 };
    __nv_bfloat16* AL[2] = { pAl0, pAl1 };
    float* HB[2] = { ph0, ph1 };

    dim3 grid(8, 16), blk(256);
    const __nv_bfloat16 *ah = pAhZ, *al = pAlZ;
    const float* hold = phZ;
    for (int s = 0; s < 256; s++) {
        int o = s & 1;
        float* hout = (s < 128) ? HB[o] : (pHdec + (size_t)(s - 128)*NB*NH);
        __nv_bfloat16 *aoh = AH[o], *aol = AL[o];
        if (s < 128) {
            k_step<20, true><<<grid, blk, SMEM_BYTES>>>(
                ah, al, pXh + (size_t)s*NB*64, pXl + (size_t)s*NB*64,
                (const uint4*)peB, nullptr, pBe, hold, hout, aoh, aol);
        } else if (s == 128) {
            k_step<16, false><<<grid, blk, SMEM_BYTES>>>(
                ah, al, nullptr, nullptr,
                (const uint4*)pd0B, pGi0, pBd0, hold, hout, aoh, aol);
        } else {
            k_step<16, false><<<grid, blk, SMEM_BYTES>>>(
                ah, al, nullptr, nullptr,
                (const uint4*)pdB, nullptr, pBd, hold, hout, aoh, aol);
        }
        ah = aoh; al = aol; hold = hout;
    }
    k_out<<<(NB*NT)/32, 256>>>(pHdec, pWT, rb, out);
}

// round 5
// speedup vs baseline: 2.5151x; 1.1078x over previous
#include <cuda_runtime.h>
#include <cuda_bf16.h>
#include <cstdint>

#define NB 512
#define NH 256
#define NT 128
#define NCTA 128

// ---------------- device scratch ----------------
__device__ __align__(128) float g_Hdec[NT*NB*NH];
__device__ __align__(128) __nv_bfloat16 g_A0h[NB*NH], g_A0l[NB*NH];
__device__ __align__(128) __nv_bfloat16 g_A1h[NB*NH], g_A1l[NB*NH];
__device__ __align__(128) __nv_bfloat16 g_Xh[256*NB*64], g_Xl[256*NB*64];
// B fragment order per jt: [part(2)][chunk(NCH)][ng(8)][lane(32)][reg(2)] u32
__device__ __align__(128) uint32_t g_eB[16*20480];      // NCH=20 (enc: Whh + Wih)
__device__ __align__(128) uint32_t g_d0B[16*20480];     // NCH=20 (dec step0: dWhh + dWih)
__device__ __align__(128) uint32_t g_dB[16*16384];      // NCH=16 (dec folded)
__device__ __align__(128) float g_Wcomb[768*256];       // reg fold temp
__device__ float g_bias_enc[1024], g_bias_dec[1024], g_bias_dec0[1024];
__device__ float g_regWT[256*64];
__device__ unsigned g_bar;

// ---------------- prep helpers ----------------
__device__ __forceinline__ uint32_t pack_split(float v0, float v1, int part) {
    __nv_bfloat16 h0 = __float2bfloat16(v0), h1 = __float2bfloat16(v1);
    if (part == 0)
        return (uint32_t)__bfloat16_as_ushort(h0) | ((uint32_t)__bfloat16_as_ushort(h1) << 16);
    __nv_bfloat16 l0 = __float2bfloat16(v0 - __bfloat162float(h0));
    __nv_bfloat16 l1 = __float2bfloat16(v1 - __bfloat162float(h1));
    return (uint32_t)__bfloat16_as_ushort(l0) | ((uint32_t)__bfloat16_as_ushort(l1) << 16);
}

// encoder-style fused weight: sec0/1: Whh+Wih (r,z); sec2: Wih only (n input); sec3: Whh only (n hidden)
__device__ __forceinline__ float gru_w(const float* Wih, const float* Whh,
                                       int sec, int j, int k) {
    if (k < 256) {
        if (sec == 0) return Whh[j*256 + k];
        if (sec == 1) return Whh[(256 + j)*256 + k];
        if (sec == 3) return Whh[(512 + j)*256 + k];
        return 0.f;
    } else {
        int f = k - 256;
        if (sec == 0) return Wih[j*64 + f];
        if (sec == 1) return Wih[(256 + j)*64 + f];
        if (sec == 2) return Wih[(512 + j)*64 + f];
        return 0.f;
    }
}

// Wcomb[n][k] = sum_f rW[f*256+k] * dWih[n*64+f]   (reg fold, coalesced)
__global__ void k_fold(const float* __restrict__ dWih, const float* __restrict__ rW)
{
    int n = blockIdx.x;           // 768 blocks
    int k = threadIdx.x;          // 256 threads
    float s = 0.f;
    #pragma unroll
    for (int f = 0; f < 64; f++) s += rW[f*256 + k] * dWih[n*64 + f];
    g_Wcomb[n*256 + k] = s;
}

__global__ void k_prep_frag(const float* __restrict__ eWih, const float* __restrict__ eWhh,
                            const float* __restrict__ dWih, const float* __restrict__ dWhh)
{
    const int stride = gridDim.x * blockDim.x;
    const int t0 = blockIdx.x * blockDim.x + threadIdx.x;

    // enc + dec0: NCH=20, per-jt u32 = 20480
    for (int i = t0; i < 16*20480; i += stride) {
        int jt = i / 20480, rem = i % 20480;
        int part = rem / 10240; rem %= 10240;
        int ch = rem / 512;     rem %= 512;
        int ng = rem / 64;      rem %= 64;
        int lane = rem >> 1, r = rem & 1;
        int k  = ch*16 + (lane & 3)*2 + r*8;
        int nl = ng*8 + (lane >> 2);
        int sec = nl & 3, j = jt*16 + (nl >> 2);
        g_eB[i]  = pack_split(gru_w(eWih, eWhh, sec, j, k), gru_w(eWih, eWhh, sec, j, k+1), part);
        g_d0B[i] = pack_split(gru_w(dWih, dWhh, sec, j, k), gru_w(dWih, dWhh, sec, j, k+1), part);
    }

    // dec folded: NCH=16, per-jt u32 = 16384
    for (int i = t0; i < 16*16384; i += stride) {
        int jt = i / 16384, rem = i % 16384;
        int part = rem / 8192; rem %= 8192;
        int ch = rem / 512;    rem %= 512;
        int ng = rem / 64;     rem %= 64;
        int lane = rem >> 1, r = rem & 1;
        int k  = ch*16 + (lane & 3)*2 + r*8;
        int nl = ng*8 + (lane >> 2);
        int sec = nl & 3, j = jt*16 + (nl >> 2);
        float v0, v1;
        if (sec == 3) {
            v0 = dWhh[(512 + j)*256 + k];
            v1 = dWhh[(512 + j)*256 + k + 1];
        } else {
            int n = sec*256 + j;
            v0 = g_Wcomb[n*256 + k]     + ((sec < 2) ? dWhh[n*256 + k]     : 0.f);
            v1 = g_Wcomb[n*256 + k + 1] + ((sec < 2) ? dWhh[n*256 + k + 1] : 0.f);
        }
        g_dB[i] = pack_split(v0, v1, part);
    }
}

// x -> bf16 hi/lo, [t][m][f]
__global__ void k_prep_x(const float* __restrict__ x)
{
    const int stride = gridDim.x * blockDim.x;
    for (int i = blockIdx.x * blockDim.x + threadIdx.x; i < 256*512*64; i += stride) {
        int t = i / (512*64); int rem = i - t*512*64;
        int m = rem >> 6, f = rem & 63;
        float v = x[(m*256 + t)*64 + f];
        __nv_bfloat16 hb = __float2bfloat16(v);
        g_Xh[i] = hb;
        g_Xl[i] = __float2bfloat16(v - __bfloat162float(hb));
    }
}

__global__ void k_prep_bias(const float* __restrict__ ebih, const float* __restrict__ ebhh,
                            const float* __restrict__ dWih,
                            const float* __restrict__ dbih, const float* __restrict__ dbhh,
                            const float* __restrict__ rW,   const float* __restrict__ rb)
{
    const int stride = gridDim.x * blockDim.x;
    const int t0 = blockIdx.x * blockDim.x + threadIdx.x;
    for (int i = t0; i < 256*64; i += stride) {
        int k = i >> 6, f = i & 63;
        g_regWT[i] = rW[f*256 + k];
    }
    for (int i = t0; i < 1024; i += stride) {
        int sec = i >> 8, j = i & 255;
        float be, bd0, bd;
        if (sec <= 1) {
            int n = sec*256 + j;
            be  = ebih[n] + ebhh[n];
            bd0 = dbih[n] + dbhh[n];
            float bc = dbih[n];
            for (int f = 0; f < 64; f++) bc += rb[f]*dWih[n*64 + f];
            bd = bc + dbhh[n];
        } else if (sec == 2) {
            int n = 512 + j;
            be = ebih[n]; bd0 = dbih[n];
            float bc = dbih[n];
            for (int f = 0; f < 64; f++) bc += rb[f]*dWih[n*64 + f];
            bd = bc;
        } else {
            int n = 512 + j;
            be = ebhh[n]; bd0 = dbhh[n]; bd = dbhh[n];
        }
        g_bias_enc[i] = be; g_bias_dec0[i] = bd0; g_bias_dec[i] = bd;
    }
}

__global__ void k_reset() { g_bar = 0u; }

// ---------------- persistent fused GRU recurrence ----------------
#define ASTRIDE 328                     // A smem row stride in bf16 (pad 8)
#define APS (64*ASTRIDE*2)              // 41984 bytes per precision part
#define SB_OFF   (2*APS)                // 83968
#define SHOLD_OFF (SB_OFF + 81920)      // 165888
#define SMEM_BYTES (SHOLD_OFF + 4096)   // 169984

#define MMA16816(d, a, b0, b1) \
    asm volatile("mma.sync.aligned.m16n8k16.row.col.f32.bf16.bf16.f32 " \
        "{%0,%1,%2,%3},{%4,%5,%6,%7},{%8,%9},{%0,%1,%2,%3};" \
        : "+f"((d)[0]), "+f"((d)[1]), "+f"((d)[2]), "+f"((d)[3]) \
        : "r"((a)[0]), "r"((a)[1]), "r"((a)[2]), "r"((a)[3]), "r"(b0), "r"(b1))

template<int NCH>
__device__ __forceinline__ void mma_chunks(const char* sm, float acc[2][2][4],
                                           int wm, int wn, int qr, int qp, int lane)
{
    const uint32_t* sBu = (const uint32_t*)(sm + SB_OFF);
    #pragma unroll 4
    for (int ch = 0; ch < NCH; ch++) {
        const int c2 = ch*16 + qp*2;
        uint32_t ah[2][4], al[2][4];
        #pragma unroll
        for (int mi = 0; mi < 2; mi++) {
            const int rr = wm*32 + mi*16 + qr;
            const char* p = sm + (rr*ASTRIDE + c2)*2;
            ah[mi][0] = *(const uint32_t*)(p);
            ah[mi][1] = *(const uint32_t*)(p + 8*ASTRIDE*2);
            ah[mi][2] = *(const uint32_t*)(p + 16);
            ah[mi][3] = *(const uint32_t*)(p + 8*ASTRIDE*2 + 16);
            al[mi][0] = *(const uint32_t*)(p + APS);
            al[mi][1] = *(const uint32_t*)(p + APS + 8*ASTRIDE*2);
            al[mi][2] = *(const uint32_t*)(p + APS + 16);
            al[mi][3] = *(const uint32_t*)(p + APS + 8*ASTRIDE*2 + 16);
        }
        #pragma unroll
        for (int ni = 0; ni < 2; ni++) {
            const int ng = wn*2 + ni;
            const uint32_t* bp = sBu + ((ch*8 + ng)*32 + lane)*2;
            uint32_t bh0 = bp[0], bh1 = bp[1];
            uint32_t bl0 = bp[NCH*512], bl1 = bp[NCH*512 + 1];
            #pragma unroll
            for (int mi = 0; mi < 2; mi++) {
                MMA16816(acc[mi][ni], ah[mi], bh0, bh1);
                MMA16816(acc[mi][ni], ah[mi], bl0, bl1);
                MMA16816(acc[mi][ni], al[mi], bh0, bh1);
            }
        }
    }
}

__global__ __launch_bounds__(256, 1) void k_persist(
    const __nv_bfloat16* __restrict__ Xh, const __nv_bfloat16* __restrict__ Xl,
    const uint4* __restrict__ eB, const uint4* __restrict__ d0B, const uint4* __restrict__ dB,
    const float* __restrict__ be, const float* __restrict__ bd0, const float* __restrict__ bd,
    float* __restrict__ Hdec,
    __nv_bfloat16* __restrict__ A0h, __nv_bfloat16* __restrict__ A0l,
    __nv_bfloat16* __restrict__ A1h, __nv_bfloat16* __restrict__ A1l)
{
    extern __shared__ char sm[];
    const int tid = threadIdx.x;
    const int bid = blockIdx.x;
    const int mt = bid & 7;
    const int jt = bid >> 3;
    const int m0 = mt*64;

    uint4* sA4h = (uint4*)sm;
    uint4* sA4l = (uint4*)(sm + APS);
    uint4* sB4  = (uint4*)(sm + SB_OFF);
    float* sHold = (float*)(sm + SHOLD_OFF);

    const int lane = tid & 31;
    const int wid  = tid >> 5;
    const int wm = wid & 1, wn = wid >> 1;
    const int qr = lane >> 2, qp = lane & 3;

    for (int i = tid; i < 1024; i += 256) sHold[i] = 0.f;

    for (int s = 0; s < 256; s++) {
        // ---- B phase load (3 times total) ----
        if (s == 0 || s == 128 || s == 129) {
            const uint4* Bsrc;
            int nB;
            if (s == 0)        { Bsrc = eB  + (size_t)jt * (20*256); nB = 20*256; }
            else if (s == 128) { Bsrc = d0B + (size_t)jt * (20*256); nB = 20*256; }
            else               { Bsrc = dB  + (size_t)jt * (16*256); nB = 16*256; }
            for (int i = tid; i < nB; i += 256) sB4[i] = Bsrc[i];
        }

        // ---- A stage (prev step's h as bf16 hi/lo) ----
        if (s == 0) {
            uint4 z = make_uint4(0, 0, 0, 0);
            #pragma unroll
            for (int i = tid; i < 2048; i += 256) {
                int r = i >> 5, c = i & 31;
                sA4h[r*41 + c] = z;
                sA4l[r*41 + c] = z;
            }
        } else {
            const uint4* Ah4 = (const uint4*)(((s - 1) & 1) ? A1h : A0h);
            const uint4* Al4 = (const uint4*)(((s - 1) & 1) ? A1l : A0l);
            #pragma unroll
            for (int i = tid; i < 2048; i += 256) {
                int r = i >> 5, c = i & 31;
                sA4h[r*41 + c] = Ah4[(m0 + r)*32 + c];
                sA4l[r*41 + c] = Al4[(m0 + r)*32 + c];
            }
        }
        // ---- X stage (encoder steps + decoder step 0 uses x127) ----
        if (s <= 128) {
            int t = (s < 128) ? s : 127;
            const uint4* Xh4 = (const uint4*)(Xh + (size_t)t*NB*64);
            const uint4* Xl4 = (const uint4*)(Xl + (size_t)t*NB*64);
            #pragma unroll
            for (int i = tid; i < 512; i += 256) {
                int r = i >> 3, c = i & 7;
                sA4h[r*41 + 32 + c] = Xh4[(m0 + r)*8 + c];
                sA4l[r*41 + 32 + c] = Xl4[(m0 + r)*8 + c];
            }
        }
        __syncthreads();

        // ---- 3-pass split-bf16 MMA ----
        float acc[2][2][4];
        #pragma unroll
        for (int a = 0; a < 2; a++)
            #pragma unroll
            for (int b = 0; b < 2; b++)
                #pragma unroll
                for (int c = 0; c < 4; c++) acc[a][b][c] = 0.f;

        if (s <= 128) mma_chunks<20>(sm, acc, wm, wn, qr, qp, lane);
        else          mma_chunks<16>(sm, acc, wm, wn, qr, qp, lane);

        const float* bias = (s < 128) ? be : ((s == 128) ? bd0 : bd);

        // ---- fused GRU epilogue; h tile persists in sHold ----
        #pragma unroll
        for (int mi = 0; mi < 2; mi++) {
            #pragma unroll
            for (int ni = 0; ni < 2; ni++) {
                float d0 = acc[mi][ni][0], d1 = acc[mi][ni][1];
                float d2 = acc[mi][ni][2], d3 = acc[mi][ni][3];
                float e0 = __shfl_xor_sync(0xffffffffu, d0, 1);
                float e1 = __shfl_xor_sync(0xffffffffu, d1, 1);
                float e2 = __shfl_xor_sync(0xffffffffu, d2, 1);
                float e3 = __shfl_xor_sync(0xffffffffu, d3, 1);
                if ((qp & 1) == 0) {
                    const int jloc = wn*4 + ni*2 + (qp >> 1);
                    const int j = jt*16 + jloc;
                    const float b0 = bias[j], b1 = bias[256 + j];
                    const float b2 = bias[512 + j], b3 = bias[768 + j];
                    #pragma unroll
                    for (int hf = 0; hf < 2; hf++) {
                        const int mloc = wm*32 + mi*16 + qr + hf*8;
                        float ga = (hf ? d2 : d0) + b0;
                        float gb = (hf ? d3 : d1) + b1;
                        float gc = (hf ? e2 : e0) + b2;
                        float gd = (hf ? e3 : e1) + b3;
                        float rg = 1.f/(1.f + __expf(-ga));
                        float zg = 1.f/(1.f + __expf(-gb));
                        float nn = tanhf(fmaf(rg, gd, gc));
                        float hv = (1.f - zg)*nn + zg*sHold[mloc*16 + jloc];
                        sHold[mloc*16 + jloc] = hv;
                    }
                }
            }
        }
        __syncthreads();

        // ---- outputs: bf16 hi/lo A for next step; fp32 Hdec for decoder ----
        __nv_bfloat16* obh = (s & 1) ? A1h : A0h;
        __nv_bfloat16* obl = (s & 1) ? A1l : A0l;
        if (tid < 64) {
            int r = tid;
            union { uint4 v; ushort u[8]; } ph[2], pl[2];
            #pragma unroll
            for (int c = 0; c < 16; c++) {
                float f = sHold[r*16 + c];
                __nv_bfloat16 hb = __float2bfloat16(f);
                __nv_bfloat16 lb = __float2bfloat16(f - __bfloat162float(hb));
                ph[c >> 3].u[c & 7] = __bfloat16_as_ushort(hb);
                pl[c >> 3].u[c & 7] = __bfloat16_as_ushort(lb);
            }
            uint4* dh = (uint4*)(obh + (size_t)(m0 + r)*256 + jt*16);
            uint4* dl = (uint4*)(obl + (size_t)(m0 + r)*256 + jt*16);
            dh[0] = ph[0].v; dh[1] = ph[1].v;
            dl[0] = pl[0].v; dl[1] = pl[1].v;
        }
        if (s >= 128) {
            int r = tid >> 2, c = tid & 3;
            float4 v = make_float4(sHold[r*16 + c*4], sHold[r*16 + c*4 + 1],
                                   sHold[r*16 + c*4 + 2], sHold[r*16 + c*4 + 3]);
            *(float4*)&Hdec[(size_t)(s - 128)*NB*NH + (size_t)(m0 + r)*256 + jt*16 + c*4] = v;
        }
        __syncthreads();

        // ---- grid barrier (monotonic counter; reset per launch by k_reset) ----
        if (tid == 0) {
            __threadfence();
            atomicAdd(&g_bar, 1u);
            unsigned target = (unsigned)(s + 1) * NCTA;
            while (*(volatile unsigned*)&g_bar < target) {}
            __threadfence();
        }
        __syncthreads();
    }
}

// ---------------- final projection ----------------
__global__ __launch_bounds__(256) void k_out(const float* __restrict__ Hdec,
                                             const float* __restrict__ regWT,
                                             const float* __restrict__ rb,
                                             float* __restrict__ out)
{
    __shared__ float hs[32][260];
    const int tid = threadIdx.x;
    const int r0 = blockIdx.x * 32;
    #pragma unroll
    for (int i = 0; i < 8; i++) {
        int g = i*256 + tid; int row = g >> 6, kq = g & 63;
        *(float4*)&hs[row][kq*4] = *(const float4*)(Hdec + (size_t)(r0 + row)*256 + kq*4);
    }
    __syncthreads();
    const int row = tid >> 3;
    const int f0 = (tid & 7)*8;
    float acc[8];
    #pragma unroll
    for (int q = 0; q < 8; q++) acc[q] = rb[f0 + q];
    for (int k = 0; k < 256; k++) {
        float hvv = hs[row][k];
        float4 w0 = *(const float4*)(regWT + k*64 + f0);
        float4 w1 = *(const float4*)(regWT + k*64 + f0 + 4);
        acc[0] += hvv*w0.x; acc[1] += hvv*w0.y; acc[2] += hvv*w0.z; acc[3] += hvv*w0.w;
        acc[4] += hvv*w1.x; acc[5] += hvv*w1.y; acc[6] += hvv*w1.z; acc[7] += hvv*w1.w;
    }
    int rr = r0 + row;
    int b = rr & 511;
    int t = rr >> 9;
    float* o = out + ((size_t)b*128 + t)*64 + f0;
    #pragma unroll
    for (int q = 0; q < 8; q++) o[q] = acc[q];
}

// ---------------- launch ----------------
extern "C" void kernel_launch(void* const* d_in, const int* in_sizes, int n_in,
                              void* d_out, int out_size)
{
    (void)in_sizes; (void)n_in; (void)out_size;
    const float* x    = (const float*)d_in[0];
    const float* eWih = (const float*)d_in[1];
    const float* eWhh = (const float*)d_in[2];
    const float* ebih = (const float*)d_in[3];
    const float* ebhh = (const float*)d_in[4];
    const float* dWih = (const float*)d_in[5];
    const float* dWhh = (const float*)d_in[6];
    const float* dbih = (const float*)d_in[7];
    const float* dbhh = (const float*)d_in[8];
    const float* rW   = (const float*)d_in[9];
    const float* rb   = (const float*)d_in[10];
    float* out = (float*)d_out;

    float *pHdec, *pBe, *pBd, *pBd0, *pWT;
    __nv_bfloat16 *pA0h, *pA0l, *pA1h, *pA1l, *pXh, *pXl;
    uint32_t *peB, *pd0B, *pdB;
    cudaGetSymbolAddress((void**)&pHdec, g_Hdec);
    cudaGetSymbolAddress((void**)&pA0h, g_A0h);
    cudaGetSymbolAddress((void**)&pA0l, g_A0l);
    cudaGetSymbolAddress((void**)&pA1h, g_A1h);
    cudaGetSymbolAddress((void**)&pA1l, g_A1l);
    cudaGetSymbolAddress((void**)&pXh, g_Xh);
    cudaGetSymbolAddress((void**)&pXl, g_Xl);
    cudaGetSymbolAddress((void**)&peB, g_eB);
    cudaGetSymbolAddress((void**)&pd0B, g_d0B);
    cudaGetSymbolAddress((void**)&pdB, g_dB);
    cudaGetSymbolAddress((void**)&pBe, g_bias_enc);
    cudaGetSymbolAddress((void**)&pBd, g_bias_dec);
    cudaGetSymbolAddress((void**)&pBd0, g_bias_dec0);
    cudaGetSymbolAddress((void**)&pWT, g_regWT);

    cudaFuncSetAttribute(k_persist, cudaFuncAttributeMaxDynamicSharedMemorySize, SMEM_BYTES);

    k_fold<<<768, 256>>>(dWih, rW);
    k_prep_frag<<<512, 256>>>(eWih, eWhh, dWih, dWhh);
    k_prep_x<<<2048, 256>>>(x);
    k_prep_bias<<<128, 256>>>(ebih, ebhh, dWih, dbih, dbhh, rW, rb);
    k_reset<<<1, 1>>>();

    k_persist<<<NCTA, 256, SMEM_BYTES>>>(
        pXh, pXl,
        (const uint4*)peB, (const uint4*)pd0B, (const uint4*)pdB,
        pBe, pBd0, pBd,
        pHdec, pA0h, pA0l, pA1h, pA1l);

    k_out<<<(NB*NT)/32, 256>>>(pHdec, pWT, rb, out);
}